// round 1
// baseline (speedup 1.0000x reference)
#include <cuda_runtime.h>
#include <math.h>

#define Bn 2
#define C 64
#define H 256
#define W 256
#define S (H*W)
#define HEADS 4
#define HD 16

// Scratch (device globals -- no allocations allowed)
__device__ float g_conv[Bn*C*S];          // deform-conv output [B,C,S]
__device__ float g_G[Bn*HEADS*HD*HD];     // raw gram q.k
__device__ float g_qn2[Bn*HEADS*HD];      // sum q^2 per row
__device__ float g_kn2[Bn*HEADS*HD];      // sum k^2 per row
__device__ float g_attn[Bn*HEADS*HD*HD];  // softmaxed attention

// ---------------------------------------------------------------------------
__global__ void zero_kernel() {
    int tid = threadIdx.x;
    for (int t = tid; t < Bn*HEADS*HD*HD; t += 256) g_G[t] = 0.f;
    for (int t = tid; t < Bn*HEADS*HD;    t += 256) { g_qn2[t] = 0.f; g_kn2[t] = 0.f; }
}

// ---------------------------------------------------------------------------
// Deformable 3x3 conv. Block = 64 pixels x 64 output channels.
// Threads 256: to = tid>>4 (output group of 4), tp = tid&15 (pixel group of 4).
// Channel chunks of 8: build s[8][64][9] in smem from 4x4 zero-padded patches,
// stage weights [8][64][9], then register-tiled 4x4 FMA (16 acc / thread).
__global__ __launch_bounds__(256, 2) void deform_conv_kernel(
    const float* __restrict__ clone, const float* __restrict__ u,
    const float* __restrict__ v, const float* __restrict__ weight)
{
    __shared__ float s_s[8][64][9];
    __shared__ float s_w[8][64][9];
    __shared__ int   s_y0[64], s_x0[64];
    __shared__ float s_wy[64], s_wx[64];

    int tid   = threadIdx.x;
    int pix0  = blockIdx.x * 64;
    int b     = pix0 / S;
    int pbase = pix0 % S;
    int to = tid >> 4, tp = tid & 15;

    if (tid < 64) {
        int p = pbase + tid;
        int y = p >> 8, x = p & 255;
        float py = (float)y + v[b*S + p];
        float px = (float)x + u[b*S + p];
        float fy = floorf(py), fx = floorf(px);
        s_y0[tid] = (int)fy; s_x0[tid] = (int)fx;
        s_wy[tid] = py - fy; s_wx[tid] = px - fx;
    }
    __syncthreads();

    float acc[4][4];
    #pragma unroll
    for (int a = 0; a < 4; a++)
        #pragma unroll
        for (int p2 = 0; p2 < 4; p2++) acc[a][p2] = 0.f;

    for (int cb = 0; cb < C; cb += 8) {
        // stage weights: global w[o][c][k] -> smem [cl][o][k]
        for (int t = tid; t < 8*64*9; t += 256) {
            int cl  = t / 576;
            int rem = t - cl*576;
            int o   = rem / 9;
            int k   = rem - o*9;
            s_w[cl][o][k] = weight[(o*C + cb + cl)*9 + k];
        }
        // build s: 512 tasks (8 ch x 64 px), 2 per thread
        #pragma unroll
        for (int rr = 0; rr < 2; rr++) {
            int t  = tid + rr*256;
            int cl = t >> 6, p = t & 63;
            const float* plane = clone + (b*C + cb + cl)*S;
            int y0 = s_y0[p], x0 = s_x0[p];
            float wy = s_wy[p], wx = s_wx[p];
            float patch[4][4];
            #pragma unroll
            for (int r = 0; r < 4; r++) {
                int yy = y0 - 1 + r;
                bool yok = ((unsigned)yy < (unsigned)H);
                const float* rowp = plane + yy*W;
                #pragma unroll
                for (int q = 0; q < 4; q++) {
                    int xx = x0 - 1 + q;
                    patch[r][q] = (yok && ((unsigned)xx < (unsigned)W)) ? __ldg(rowp + xx) : 0.f;
                }
            }
            float hx[4][3];
            #pragma unroll
            for (int r = 0; r < 4; r++)
                #pragma unroll
                for (int kx = 0; kx < 3; kx++)
                    hx[r][kx] = patch[r][kx] + wx*(patch[r][kx+1] - patch[r][kx]);
            #pragma unroll
            for (int ky = 0; ky < 3; ky++)
                #pragma unroll
                for (int kx = 0; kx < 3; kx++)
                    s_s[cl][p][ky*3+kx] = hx[ky][kx] + wy*(hx[ky+1][kx] - hx[ky][kx]);
        }
        __syncthreads();

        #pragma unroll 2
        for (int cl = 0; cl < 8; ++cl) {
            float sv[4][9], wv[4][9];
            #pragma unroll
            for (int pp = 0; pp < 4; ++pp)
                #pragma unroll
                for (int k = 0; k < 9; ++k) sv[pp][k] = s_s[cl][tp*4+pp][k];
            #pragma unroll
            for (int oo = 0; oo < 4; ++oo)
                #pragma unroll
                for (int k = 0; k < 9; ++k) wv[oo][k] = s_w[cl][to*4+oo][k];
            #pragma unroll
            for (int k = 0; k < 9; ++k)
                #pragma unroll
                for (int oo = 0; oo < 4; ++oo)
                    #pragma unroll
                    for (int pp = 0; pp < 4; ++pp)
                        acc[oo][pp] += wv[oo][k]*sv[pp][k];
        }
        __syncthreads();
    }

    #pragma unroll
    for (int oo = 0; oo < 4; ++oo) {
        float4 vst = make_float4(acc[oo][0], acc[oo][1], acc[oo][2], acc[oo][3]);
        *(float4*)&g_conv[(b*C + to*4+oo)*S + pbase + tp*4] = vst;
    }
}

// ---------------------------------------------------------------------------
// Gram + norms: per (b,h) compute G[16][16] = q_i . k_j over S, plus sum q^2,
// sum k^2 per row. Split S into 32 slices of 2048; atomic partial reduction.
__global__ __launch_bounds__(256) void dots_kernel(const float* __restrict__ xg) {
    __shared__ float qs[16][260];
    __shared__ float ks[16][260];
    __shared__ float s_nq[16], s_nk[16];

    int tid = threadIdx.x;
    int bh  = blockIdx.x >> 5;
    int sl  = blockIdx.x & 31;
    int b   = bh >> 2, hh = bh & 3;
    int i = tid >> 4, j = tid & 15;
    int s0 = sl * 2048;

    if (tid < 16) { s_nq[tid] = 0.f; s_nk[tid] = 0.f; }

    float g = 0.f, nqp = 0.f, nkp = 0.f;
    for (int ch = 0; ch < 8; ++ch) {
        __syncthreads();
        int sbase = s0 + ch*256;
        #pragma unroll
        for (int e = 0; e < 8; ++e) {
            int lin = tid + e*256;          // float4 unit, 0..2047
            int r = lin >> 6, c4 = lin & 63;
            const float* src = (r < 16)
                ? (xg     + (b*C + hh*HD + r)*S)
                : (g_conv + (b*C + hh*HD + (r-16))*S);
            float4 val = *(const float4*)(src + sbase + c4*4);
            float* dst = (r < 16) ? &qs[r][c4*4] : &ks[r-16][c4*4];
            dst[0] = val.x; dst[1] = val.y; dst[2] = val.z; dst[3] = val.w;
        }
        __syncthreads();
        #pragma unroll 8
        for (int s = 0; s < 256; s += 4) {
            float4 qv = *(const float4*)&qs[i][s];
            float4 kv = *(const float4*)&ks[j][s];
            g += qv.x*kv.x; g += qv.y*kv.y; g += qv.z*kv.z; g += qv.w*kv.w;
        }
        #pragma unroll 4
        for (int s = j; s < 256; s += 16) { float q0 = qs[i][s]; nqp += q0*q0; }
        #pragma unroll 4
        for (int s = i; s < 256; s += 16) { float k0 = ks[j][s]; nkp += k0*k0; }
    }
    atomicAdd(&g_G[bh*256 + i*16 + j], g);
    atomicAdd(&s_nq[i], nqp);
    atomicAdd(&s_nk[j], nkp);
    __syncthreads();
    if (tid < 16)       atomicAdd(&g_qn2[bh*16 + tid], s_nq[tid]);
    else if (tid < 32)  atomicAdd(&g_kn2[bh*16 + tid-16], s_nk[tid-16]);
}

// ---------------------------------------------------------------------------
// Normalize + temperature + stable softmax. 8 (b,h) groups x 16 rows.
__global__ void softmax_kernel(const float* __restrict__ temp) {
    int tid = threadIdx.x;         // 256 threads
    int bh = tid >> 5, lane = tid & 31;
    if (lane >= 16) return;
    int i  = lane;
    int hh = bh & 3;
    float dq = fmaxf(sqrtf(g_qn2[bh*16 + i]), 1e-12f);
    float T  = temp[hh];
    float logit[16];
    float mx = -1e30f;
    #pragma unroll
    for (int jj = 0; jj < 16; ++jj) {
        float dk = fmaxf(sqrtf(g_kn2[bh*16 + jj]), 1e-12f);
        float l  = g_G[bh*256 + i*16 + jj] / (dq*dk) * T;
        logit[jj] = l; mx = fmaxf(mx, l);
    }
    float sum = 0.f;
    #pragma unroll
    for (int jj = 0; jj < 16; ++jj) { float e = expf(logit[jj]-mx); logit[jj] = e; sum += e; }
    float inv = 1.f/sum;
    #pragma unroll
    for (int jj = 0; jj < 16; ++jj) g_attn[bh*256 + i*16 + jj] = logit[jj]*inv;
}

// ---------------------------------------------------------------------------
// out[c,s] = sum_d attn[c,d] * kv[d,s]. Attn rows held in registers.
__global__ __launch_bounds__(256) void out_kernel(float* __restrict__ out) {
    int tid = threadIdx.x;
    int bh = blockIdx.x >> 5;      // 32 s-tiles of 2048
    int st = blockIdx.x & 31;
    int b = bh >> 2, hh = bh & 3;
    int ig = tid >> 6, scol = tid & 63;

    float a[4][16];
    #pragma unroll
    for (int ii = 0; ii < 4; ++ii)
        #pragma unroll
        for (int d = 0; d < 16; ++d)
            a[ii][d] = g_attn[bh*256 + (ig*4+ii)*16 + d];

    int sbase0 = st * 2048;
    for (int sb = 0; sb < 32; ++sb) {
        int s = sbase0 + sb*64 + scol;
        float accv[4] = {0.f, 0.f, 0.f, 0.f};
        #pragma unroll
        for (int d = 0; d < 16; ++d) {
            float kvv = g_conv[(b*C + hh*HD + d)*S + s];
            #pragma unroll
            for (int ii = 0; ii < 4; ++ii) accv[ii] += a[ii][d]*kvv;
        }
        #pragma unroll
        for (int ii = 0; ii < 4; ++ii)
            out[(b*C + hh*HD + ig*4+ii)*S + s] = accv[ii];
    }
}

// ---------------------------------------------------------------------------
extern "C" void kernel_launch(void* const* d_in, const int* in_sizes, int n_in,
                              void* d_out, int out_size) {
    const float* clone  = (const float*)d_in[0];
    const float* xg     = (const float*)d_in[1];
    const float* u      = (const float*)d_in[2];
    const float* v      = (const float*)d_in[3];
    const float* weight = (const float*)d_in[4];
    const float* temp   = (const float*)d_in[5];
    float* out = (float*)d_out;

    zero_kernel<<<1, 256>>>();
    deform_conv_kernel<<<Bn*S/64, 256>>>(clone, u, v, weight);
    dots_kernel<<<Bn*HEADS*32, 256>>>(xg);
    softmax_kernel<<<1, 256>>>(temp);
    out_kernel<<<Bn*HEADS*32, 256>>>(out);
}